// round 1
// baseline (speedup 1.0000x reference)
#include <cuda_runtime.h>

#define BATCH 1024
#define NB 8            // batches per block
#define NTH 256         // threads per block (each owns 2 gate rows)
#define HID 128
#define G4  512         // 4*HID gate rows
#define KS  80          // W_hh cols cached in smem
#define KSP 84          // padded smem row stride (conflict-free LDS.128)
#define GP  10          // gates smem row stride (conflict-free STS.64)
#define DTC 0.1f
#define Q0V 0.01f
#define RV  0.25f

// shared memory layout (float offsets)
#define O_WHH   0                      // 512*84 = 43008
#define O_GATES 43008                  // 512*10 = 5120
#define O_H     48128                  // 128*8  = 1024   (h stored [k][b])
#define O_WIH   49152                  // 1024
#define O_BIAS  50176                  // 512 (b_ih+b_hh)
#define O_WFC   50688                  // 1280
#define O_QT    51968                  // 160
#define O_IN    52128                  // 16
#define O_SIG   52144                  // 80
#define O_BFC   52224                  // 10
#define SMEM_FLOATS 52240
#define SMEM_BYTES (SMEM_FLOATS * 4)   // 208,960 B < 227KB

typedef unsigned long long ull;

__device__ __forceinline__ float tanh_ap(float x) {
    float y; asm("tanh.approx.f32 %0, %1;" : "=f"(y) : "f"(x)); return y;
}
__device__ __forceinline__ float sigm(float x) {
    return fmaf(tanh_ap(0.5f * x), 0.5f, 0.5f);
}
__device__ __forceinline__ ull pk2(float x) {
    ull r; asm("mov.b64 %0, {%1, %1};" : "=l"(r) : "f"(x)); return r;
}
__device__ __forceinline__ ull pkab(float lo, float hi) {
    ull r; asm("mov.b64 %0, {%1, %2};" : "=l"(r) : "f"(lo), "f"(hi)); return r;
}
#define FMA2(acc, w, h) asm("fma.rn.f32x2 %0, %1, %2, %0;" : "+l"(acc) : "l"(w), "l"(h))

__global__ void __launch_bounds__(NTH, 1) nnakf_kernel(
    const float* __restrict__ meas, const float* __restrict__ Qt,
    const float* __restrict__ Wih,  const float* __restrict__ Whh,
    const float* __restrict__ bih,  const float* __restrict__ bhh,
    const float* __restrict__ Wfc,  const float* __restrict__ bfc,
    float* __restrict__ out, int T)
{
    extern __shared__ float smem[];
    const int tid = threadIdx.x;

    // ---- one-time setup: stage weights in smem ----
    for (int idx = tid; idx < G4 * KS; idx += NTH) {
        int r = idx / KS, c = idx - r * KS;
        smem[O_WHH + r * KSP + c] = Whh[r * HID + c];
    }
    for (int idx = tid; idx < G4 * 2; idx += NTH) smem[O_WIH + idx] = Wih[idx];
    for (int idx = tid; idx < G4;     idx += NTH) smem[O_BIAS + idx] = bih[idx] + bhh[idx];
    for (int idx = tid; idx < 10*HID; idx += NTH) smem[O_WFC + idx] = Wfc[idx];
    for (int idx = tid; idx < 160;    idx += NTH) smem[O_QT + idx] = Qt[idx];
    if (tid < 10) smem[O_BFC + tid] = bfc[tid];
    for (int idx = tid; idx < HID*NB; idx += NTH) smem[O_H + idx] = 0.0f;
    __syncthreads();

    const int r0 = tid, r1 = tid + NTH;
    const float rb0 = smem[O_BIAS + r0], rb1 = smem[O_BIAS + r1];
    const float wi00 = smem[O_WIH + 2*r0], wi01 = smem[O_WIH + 2*r0 + 1];
    const float wi10 = smem[O_WIH + 2*r1], wi11 = smem[O_WIH + 2*r1 + 1];

    float creg[4] = {0.f, 0.f, 0.f, 0.f};     // LSTM c state (4 (hid,b) items/thread)
    float x[4]  = {0.f, 0.f, 0.f, 0.f};       // Kalman state (threads 0..7)
    float Pm[16];
    #pragma unroll
    for (int e = 0; e < 16; e++) Pm[e] = (e % 5 == 0) ? 1.0f : 0.0f;

    const size_t gb = (size_t)blockIdx.x * NB + tid;   // global batch (valid tid<8)

    for (int t = 0; t < T; t++) {
        float Ppf[16], xp0, xp1, xp2, xp3, iv0, iv1;

        // ---- C1: Kalman predict + innovation (threads 0..7) ----
        if (tid < NB) {
            xp0 = x[0] + DTC * x[2]; xp1 = x[1] + DTC * x[3];
            xp2 = x[2]; xp3 = x[3];
            float A[16];
            #pragma unroll
            for (int j = 0; j < 4; j++) {
                A[j]      = Pm[j]     + DTC * Pm[8 + j];
                A[4 + j]  = Pm[4 + j] + DTC * Pm[12 + j];
                A[8 + j]  = Pm[8 + j];
                A[12 + j] = Pm[12 + j];
            }
            #pragma unroll
            for (int i = 0; i < 4; i++) {
                Ppf[i*4+0] = A[i*4+0] + DTC * A[i*4+2];
                Ppf[i*4+1] = A[i*4+1] + DTC * A[i*4+3];
                Ppf[i*4+2] = A[i*4+2];
                Ppf[i*4+3] = A[i*4+3];
            }
            Ppf[0] += Q0V; Ppf[5] += Q0V; Ppf[10] += Q0V; Ppf[15] += Q0V;
            float2 z = *(const float2*)(meas + (gb * (size_t)T + t) * 2);
            iv0 = z.x - xp0; iv1 = z.y - xp1;
            smem[O_IN + 2*tid]     = iv0 * iv0 / (Ppf[0] + RV);
            smem[O_IN + 2*tid + 1] = iv1 * iv1 / (Ppf[5] + RV);
        }
        __syncthreads();

        // ---- Phase A: gates = In@Wih^T + bias + h@Whh^T (f32x2 packed) ----
        ull a00, a01, a02, a03, a10, a11, a12, a13;
        {
            float s0[NB], s1[NB];
            #pragma unroll
            for (int b = 0; b < NB; b++) {
                float i0 = smem[O_IN + 2*b], i1 = smem[O_IN + 2*b + 1];
                s0[b] = fmaf(wi01, i1, fmaf(wi00, i0, rb0));
                s1[b] = fmaf(wi11, i1, fmaf(wi10, i0, rb1));
            }
            a00 = pkab(s0[0], s0[1]); a01 = pkab(s0[2], s0[3]);
            a02 = pkab(s0[4], s0[5]); a03 = pkab(s0[6], s0[7]);
            a10 = pkab(s1[0], s1[1]); a11 = pkab(s1[2], s1[3]);
            a12 = pkab(s1[4], s1[5]); a13 = pkab(s1[6], s1[7]);
        }
        #pragma unroll
        for (int kc = 0; kc < HID / 4; kc++) {
            const int k = kc * 4;
            float4 w0, w1;
            if (k < KS) {   // compile-time resolved under full unroll
                w0 = *(const float4*)&smem[O_WHH + r0 * KSP + k];
                w1 = *(const float4*)&smem[O_WHH + r1 * KSP + k];
            } else {
                w0 = __ldg((const float4*)(Whh + r0 * HID + k));
                w1 = __ldg((const float4*)(Whh + r1 * HID + k));
            }
            #pragma unroll
            for (int u = 0; u < 4; u++) {
                float w0u = (&w0.x)[u], w1u = (&w1.x)[u];
                ull wp0 = pk2(w0u), wp1 = pk2(w1u);
                ulonglong2 ha = *(const ulonglong2*)&smem[O_H + (k + u) * NB];
                ulonglong2 hb = *(const ulonglong2*)&smem[O_H + (k + u) * NB + 4];
                FMA2(a00, wp0, ha.x); FMA2(a01, wp0, ha.y);
                FMA2(a02, wp0, hb.x); FMA2(a03, wp0, hb.y);
                FMA2(a10, wp1, ha.x); FMA2(a11, wp1, ha.y);
                FMA2(a12, wp1, hb.x); FMA2(a13, wp1, hb.y);
            }
        }
        {
            ull* g0 = (ull*)&smem[O_GATES + r0 * GP];
            g0[0] = a00; g0[1] = a01; g0[2] = a02; g0[3] = a03;
            ull* g1 = (ull*)&smem[O_GATES + r1 * GP];
            g1[0] = a10; g1[1] = a11; g1[2] = a12; g1[3] = a13;
        }
        __syncthreads();

        // ---- Phase A2: c/h update (all threads, 4 items each) ----
        #pragma unroll
        for (int q = 0; q < 4; q++) {
            int m = q * NTH + tid;
            int hid = m & (HID - 1), b = m >> 7;
            float gi = smem[O_GATES + hid * GP + b];
            float gf = smem[O_GATES + (HID + hid) * GP + b];
            float gg = smem[O_GATES + (2*HID + hid) * GP + b];
            float go = smem[O_GATES + (3*HID + hid) * GP + b];
            float c = sigm(gf) * creg[q] + sigm(gi) * tanh_ap(gg);
            creg[q] = c;
            smem[O_H + hid * NB + b] = sigm(go) * tanh_ap(c);
        }
        __syncthreads();

        // ---- Phase B: sigma = sigmoid(h @ Wfc^T + bfc) ----
        if (tid < 80) {
            int b = tid & 7, n = tid >> 3;
            const float* wf = &smem[O_WFC + n * HID];
            float q0 = 0.f, q1 = 0.f, q2 = 0.f, q3 = 0.f;
            #pragma unroll
            for (int k = 0; k < HID; k += 4) {
                q0 = fmaf(smem[O_H + (k+0) * NB + b], wf[k+0], q0);
                q1 = fmaf(smem[O_H + (k+1) * NB + b], wf[k+1], q1);
                q2 = fmaf(smem[O_H + (k+2) * NB + b], wf[k+2], q2);
                q3 = fmaf(smem[O_H + (k+3) * NB + b], wf[k+3], q3);
            }
            smem[O_SIG + b * 10 + n] = sigm((q0 + q1) + (q2 + q3) + smem[O_BFC + n]);
        }
        __syncthreads();

        // ---- C2: Q-adapt + Kalman update + output (threads 0..7) ----
        if (tid < NB) {
            #pragma unroll
            for (int n = 0; n < 10; n++) {
                float sn = smem[O_SIG + tid * 10 + n];
                #pragma unroll
                for (int e = 0; e < 16; e++)
                    Ppf[e] = fmaf(sn, smem[O_QT + n * 16 + e], Ppf[e]);
            }
            float S00 = Ppf[0] + RV, S01 = Ppf[1], S10 = Ppf[4], S11 = Ppf[5] + RV;
            float rdet = 1.0f / (S00 * S11 - S01 * S10);
            float K0[4], K1[4];
            #pragma unroll
            for (int i = 0; i < 4; i++) {
                K0[i] = (Ppf[i*4 + 0] * S11 - Ppf[i*4 + 1] * S10) * rdet;
                K1[i] = (Ppf[i*4 + 1] * S00 - Ppf[i*4 + 0] * S01) * rdet;
            }
            x[0] = xp0 + K0[0] * iv0 + K1[0] * iv1;
            x[1] = xp1 + K0[1] * iv0 + K1[1] * iv1;
            x[2] = xp2 + K0[2] * iv0 + K1[2] * iv1;
            x[3] = xp3 + K0[3] * iv0 + K1[3] * iv1;
            #pragma unroll
            for (int i = 0; i < 4; i++) {
                #pragma unroll
                for (int j = 0; j < 4; j++)
                    Pm[i*4 + j] = Ppf[i*4 + j] - K0[i] * Ppf[j] - K1[i] * Ppf[4 + j];
            }
            *(float4*)(out + (gb * (size_t)T + t) * 4) =
                make_float4(x[0], x[1], x[2], x[3]);
        }
        // no barrier needed here: next C1 only writes In_s (last read before S2
        // of this iter) and runs on the same threads as C2.
    }
}

extern "C" void kernel_launch(void* const* d_in, const int* in_sizes, int n_in,
                              void* d_out, int out_size) {
    const float* meas = (const float*)d_in[0];
    const float* Qt   = (const float*)d_in[1];
    const float* Wih  = (const float*)d_in[2];
    const float* Whh  = (const float*)d_in[3];
    const float* bih  = (const float*)d_in[4];
    const float* bhh  = (const float*)d_in[5];
    const float* Wfc  = (const float*)d_in[6];
    const float* bfc  = (const float*)d_in[7];
    float* out = (float*)d_out;
    int T = in_sizes[0] / (BATCH * 2);   // 512 for the reference shapes

    cudaFuncSetAttribute(nnakf_kernel,
                         cudaFuncAttributeMaxDynamicSharedMemorySize, SMEM_BYTES);
    nnakf_kernel<<<BATCH / NB, NTH, SMEM_BYTES>>>(
        meas, Qt, Wih, Whh, bih, bhh, Wfc, bfc, out, T);
}